// round 15
// baseline (speedup 1.0000x reference)
#include <cuda_runtime.h>
#include <cuda_bf16.h>
#include <math.h>

#define N_ITER 32768
#define NB 257
#define PIANO 8388608
#define CHUNK 32
#define WARM 8
#define FPB 4        // frames per CTA in fwd
#define SEGS 7       // output segments per CTA in inv (8 frames per CTA)

// padded shared index: break 32-float bank periodicity
#define SP(i) ((i) + ((i) >> 5))

#define GBAR(id) asm volatile("bar.sync %0, 64;" :: "r"(id) : "memory")

// Frequency-domain scratch (static __device__ arrays — no allocs allowed).
__device__ float g_ehr[N_ITER * NB];
__device__ float g_ehi[N_ITER * NB];
__device__ float g_zr[N_ITER * NB];
__device__ float g_zi[N_ITER * NB];
__device__ float g_twc[257], g_tws[257];   // e^{-i*pi*k/256}

__global__ void tw_init_kernel() {
    int k = threadIdx.x;
    if (k < 257) {
        float s, c;
        sincospif(-(float)k / 256.f, &s, &c);
        g_twc[k] = c; g_tws[k] = s;
    }
}

// ---------------------------------------------------------------------------
// Kernel 1: impulse gen + 512-pt real FFT as 256-pt complex radix-4 Stockham.
// Stage 0 fused with global load; stage 3 twiddle-free. Group-local named
// barriers decouple the 4 frames per 256-thread CTA.
// ---------------------------------------------------------------------------
__global__ void __launch_bounds__(256) fwd_kernel(const float* __restrict__ noise,
                                                  const float* __restrict__ env) {
    __shared__ float Ar[FPB][264], Ai[FPB][264], Br[FPB][264], Bi[FPB][264];
    __shared__ float twc[257], tws[257];
    int t = threadIdx.x & 63, g = threadIdx.x >> 6;
    int bid = g + 1;
    int f = blockIdx.x * FPB + g;

    { int k = threadIdx.x;
      twc[k] = g_twc[k]; tws[k] = g_tws[k];
      if (k == 0) { twc[256] = g_twc[256]; tws[256] = g_tws[256]; } }

    float e = env[f];
    float amp = e * e;
    const float2* nf2 = (const float2*)(noise + (size_t)f * 512);
    float x0r, x0i, x1r, x1i, x2r, x2i, x3r, x3i;
    { float2 v = nf2[t];       x0r = (2.f*v.x-1.f)*amp; x0i = (2.f*v.y-1.f)*amp; }
    { float2 v = nf2[t + 64];  x1r = (2.f*v.x-1.f)*amp; x1i = (2.f*v.y-1.f)*amp; }
    { float2 v = nf2[t + 128]; x2r = (2.f*v.x-1.f)*amp; x2i = (2.f*v.y-1.f)*amp; }
    { float2 v = nf2[t + 192]; x3r = (2.f*v.x-1.f)*amp; x3i = (2.f*v.y-1.f)*amp; }
    __syncthreads();   // table ready (block-wide, once)

    // Stage 0 (m=1, j=t) in registers -> A.
    {
        float t0r = x0r + x2r, t0i = x0i + x2i;
        float t1r = x0r - x2r, t1i = x0i - x2i;
        float t2r = x1r + x3r, t2i = x1i + x3i;
        float t3r = x1r - x3r, t3i = x1i - x3i;
        float y0r = t0r + t2r, y0i = t0i + t2i;
        float u1r = t1r + t3i, u1i = t1i - t3r;
        float u2r = t0r - t2r, u2i = t0i - t2i;
        float u3r = t1r - t3i, u3i = t1i + t3r;
        float w1c = twc[2 * t], w1s = tws[2 * t];
        float w2c = w1c*w1c - w1s*w1s, w2s = 2.f*w1c*w1s;
        float w3c = w2c*w1c - w2s*w1s, w3s = w2c*w1s + w2s*w1c;
        int o = 4 * t;
        Ar[g][SP(o)]   = y0r;                  Ai[g][SP(o)]   = y0i;
        Ar[g][SP(o+1)] = u1r*w1c - u1i*w1s;    Ai[g][SP(o+1)] = u1r*w1s + u1i*w1c;
        Ar[g][SP(o+2)] = u2r*w2c - u2i*w2s;    Ai[g][SP(o+2)] = u2r*w2s + u2i*w2c;
        Ar[g][SP(o+3)] = u3r*w3c - u3i*w3s;    Ai[g][SP(o+3)] = u3r*w3s + u3i*w3c;
    }
    GBAR(bid);

    // Stages 1-2 through shared (A->B->A).
#pragma unroll
    for (int r = 1; r < 3; ++r) {
        int m = 1 << (2 * r);
        int k = t & (m - 1);
        int j = t >> (2 * r);
        const float (*srcr)[264] = (r == 1) ? Ar : Br;
        const float (*srci)[264] = (r == 1) ? Ai : Bi;
        float (*dstr)[264] = (r == 1) ? Br : Ar;
        float (*dsti)[264] = (r == 1) ? Bi : Ai;
        float a0r = srcr[g][SP(t)],       a0i = srci[g][SP(t)];
        float a1r = srcr[g][SP(t + 64)],  a1i = srci[g][SP(t + 64)];
        float a2r = srcr[g][SP(t + 128)], a2i = srci[g][SP(t + 128)];
        float a3r = srcr[g][SP(t + 192)], a3i = srci[g][SP(t + 192)];
        float t0r = a0r + a2r, t0i = a0i + a2i;
        float t1r = a0r - a2r, t1i = a0i - a2i;
        float t2r = a1r + a3r, t2i = a1i + a3i;
        float t3r = a1r - a3r, t3i = a1i - a3i;
        float y0r = t0r + t2r, y0i = t0i + t2i;
        float u1r = t1r + t3i, u1i = t1i - t3r;
        float u2r = t0r - t2r, u2i = t0i - t2i;
        float u3r = t1r - t3i, u3i = t1i + t3r;
        int idx = 2 * j * m;
        float w1c = twc[idx], w1s = tws[idx];
        float w2c = w1c*w1c - w1s*w1s, w2s = 2.f*w1c*w1s;
        float w3c = w2c*w1c - w2s*w1s, w3s = w2c*w1s + w2s*w1c;
        int o = 4 * m * j + k;
        dstr[g][SP(o)]       = y0r;                  dsti[g][SP(o)]       = y0i;
        dstr[g][SP(o+m)]     = u1r*w1c - u1i*w1s;    dsti[g][SP(o+m)]     = u1r*w1s + u1i*w1c;
        dstr[g][SP(o+2*m)]   = u2r*w2c - u2i*w2s;    dsti[g][SP(o+2*m)]   = u2r*w2s + u2i*w2c;
        dstr[g][SP(o+3*m)]   = u3r*w3c - u3i*w3s;    dsti[g][SP(o+3*m)]   = u3r*w3s + u3i*w3c;
        GBAR(bid);
    }

    // Stage 3 (m=64, j=0: twiddles = 1) -> Z[t+64h] unpadded in B.
    {
        float a0r = Ar[g][SP(t)],       a0i = Ai[g][SP(t)];
        float a1r = Ar[g][SP(t + 64)],  a1i = Ai[g][SP(t + 64)];
        float a2r = Ar[g][SP(t + 128)], a2i = Ai[g][SP(t + 128)];
        float a3r = Ar[g][SP(t + 192)], a3i = Ai[g][SP(t + 192)];
        float t0r = a0r + a2r, t0i = a0i + a2i;
        float t1r = a0r - a2r, t1i = a0i - a2i;
        float t2r = a1r + a3r, t2i = a1i + a3i;
        float t3r = a1r - a3r, t3i = a1i - a3i;
        Br[g][t]       = t0r + t2r;  Bi[g][t]       = t0i + t2i;
        Br[g][t + 64]  = t1r + t3i;  Bi[g][t + 64]  = t1i - t3r;
        Br[g][t + 128] = t0r - t2r;  Bi[g][t + 128] = t0i - t2i;
        Br[g][t + 192] = t1r - t3i;  Bi[g][t + 192] = t1i + t3r;
    }
    GBAR(bid);

    // Untangle 256-pt complex FFT Z into 257-bin rfft.
    float* ehr = g_ehr + (size_t)f * NB;
    float* ehi = g_ehi + (size_t)f * NB;
#pragma unroll
    for (int h = 0; h < 4; ++h) {
        int k = t + 64 * h;
        int k2 = (256 - k) & 255;
        float Arv = Br[g][k],  Aiv = Bi[g][k];
        float Crv = Br[g][k2], Civ = Bi[g][k2];
        float Xer = 0.5f * (Arv + Crv), Xei = 0.5f * (Aiv - Civ);
        float Dr  = 0.5f * (Arv - Crv), Di  = 0.5f * (Aiv + Civ);
        float Xor = Di, Xoi = -Dr;                 // -i*D
        float c = twc[k], s = tws[k];
        ehr[k] = Xer + Xor * c - Xoi * s;
        ehi[k] = Xei + Xor * s + Xoi * c;
    }
    if (t == 0) {
        ehr[256] = Br[g][0] - Bi[g][0];
        ehi[256] = 0.f;
    }
}

// ---------------------------------------------------------------------------
// Kernel 2: chunk-parallel frequency-domain recurrence.
// ---------------------------------------------------------------------------
__global__ void __launch_bounds__(288) recur_kernel(const float* __restrict__ tfr_g,
                                                    const float* __restrict__ tfi_g) {
    __shared__ float2 gbuf[2][260];
    int c = blockIdx.x, t = threadIdx.x;
    int start = c * CHUNK;
    int i0 = start - WARM;
    if (i0 < 0) i0 = 0;
    int end = start + CHUNK;
    bool act = (t < NB);
    int k = act ? t : 0;

    float yr = 0.f, yi = 0.f;
    float er = 0.f, ei = 0.f, tr = 0.f, ti = 0.f;
    if (act) {
        size_t b = (size_t)i0 * NB + k;
        er = g_ehr[b]; ei = g_ehi[b];
        tr = tfr_g[b]; ti = tfi_g[b];
    }
    int p = 0;
    for (int i = i0; i < end; ++i) {
        float cer = er, cei = ei, ctr = tr, cti = ti;
        if (act && (i + 1 < end)) {
            size_t b2 = (size_t)(i + 1) * NB + k;
            er = g_ehr[b2]; ei = g_ehi[b2];
            tr = tfr_g[b2]; ti = tfi_g[b2];
        }
        float zr = yr + cer, zi = yi + cei;
        if (act && i >= start) {
            size_t bo = (size_t)i * NB + k;
            g_zr[bo] = zr;
            g_zi[bo] = zi;
        }
        float gr = ctr * zr - cti * zi;
        float gi = ctr * zi + cti * zr;
        if (k == 0 || k == 256) gi = 0.f;
        if (act) {
            gbuf[p][k + 1] = make_float2(gr, gi);
            if (k == 1)   gbuf[p][0]   = make_float2(gr, -gi);
            if (k == 255) gbuf[p][258] = make_float2(gr, -gi);
        }
        __syncthreads();
        if (act) {
            float2 L = gbuf[p][k];
            float2 R = gbuf[p][k + 2];
            yr = 0.54f * gr - 0.23f * (L.x + R.x);
            yi = 0.54f * gi - 0.23f * (L.y + R.y);
        }
        p ^= 1;
    }
}

// ---------------------------------------------------------------------------
// 512-pt irfft for one frame (64-thread group). Produces x[2n]+i*x[2n+1] at
// n = t+64h in v[h]. Uses group-local named barrier `bid`.
// ---------------------------------------------------------------------------
__device__ __forceinline__ void irfft512(const float* __restrict__ zr,
                                         const float* __restrict__ zi,
                                         float* __restrict__ Ar_, float* __restrict__ Ai_,
                                         float* __restrict__ Br_, float* __restrict__ Bi_,
                                         const float* __restrict__ twc,
                                         const float* __restrict__ tws,
                                         int t, int bid, float2 v[4]) {
    for (int k = t; k < 257; k += 64) { Br_[k] = zr[k]; Bi_[k] = zi[k]; }
    GBAR(bid);

    // Untangle -> Z[k] (regs) then stage 0 -> A.
    float zkr[4], zki[4];
#pragma unroll
    for (int h = 0; h < 4; ++h) {
        int k = t + 64 * h;
        float Arv = Br_[k],       Aiv = Bi_[k];
        float Crv = Br_[256 - k], Civ = Bi_[256 - k];
        float Xer = 0.5f * (Arv + Crv), Xei = 0.5f * (Aiv - Civ);
        float Dr  = 0.5f * (Arv - Crv), Di  = 0.5f * (Aiv + Civ);
        float c = twc[k], s = -tws[k];            // e^{+i*pi*k/256}
        float Xor = Dr * c - Di * s;
        float Xoi = Dr * s + Di * c;
        zkr[h] = (Xer - Xoi) * (1.f / 256.f);
        zki[h] = (Xei + Xor) * (1.f / 256.f);
    }
    {
        float t0r = zkr[0] + zkr[2], t0i = zki[0] + zki[2];
        float t1r = zkr[0] - zkr[2], t1i = zki[0] - zki[2];
        float t2r = zkr[1] + zkr[3], t2i = zki[1] + zki[3];
        float t3r = zkr[1] - zkr[3], t3i = zki[1] - zki[3];
        float y0r = t0r + t2r, y0i = t0i + t2i;
        float u1r = t1r - t3i, u1i = t1i + t3r;   // inverse orientation
        float u2r = t0r - t2r, u2i = t0i - t2i;
        float u3r = t1r + t3i, u3i = t1i - t3r;
        float w1c = twc[2 * t], w1s = -tws[2 * t];
        float w2c = w1c*w1c - w1s*w1s, w2s = 2.f*w1c*w1s;
        float w3c = w2c*w1c - w2s*w1s, w3s = w2c*w1s + w2s*w1c;
        int o = 4 * t;
        Ar_[SP(o)]   = y0r;                  Ai_[SP(o)]   = y0i;
        Ar_[SP(o+1)] = u1r*w1c - u1i*w1s;    Ai_[SP(o+1)] = u1r*w1s + u1i*w1c;
        Ar_[SP(o+2)] = u2r*w2c - u2i*w2s;    Ai_[SP(o+2)] = u2r*w2s + u2i*w2c;
        Ar_[SP(o+3)] = u3r*w3c - u3i*w3s;    Ai_[SP(o+3)] = u3r*w3s + u3i*w3c;
    }
    GBAR(bid);

    // Stages 1-2 (A->B->A), inverse twiddles.
#pragma unroll
    for (int r = 1; r < 3; ++r) {
        int m = 1 << (2 * r);
        int k = t & (m - 1);
        int j = t >> (2 * r);
        const float* sr = (r == 1) ? Ar_ : Br_;
        const float* si = (r == 1) ? Ai_ : Bi_;
        float* dr = (r == 1) ? Br_ : Ar_;
        float* di = (r == 1) ? Bi_ : Ai_;
        float a0r = sr[SP(t)],       a0i = si[SP(t)];
        float a1r = sr[SP(t + 64)],  a1i = si[SP(t + 64)];
        float a2r = sr[SP(t + 128)], a2i = si[SP(t + 128)];
        float a3r = sr[SP(t + 192)], a3i = si[SP(t + 192)];
        float t0r = a0r + a2r, t0i = a0i + a2i;
        float t1r = a0r - a2r, t1i = a0i - a2i;
        float t2r = a1r + a3r, t2i = a1i + a3i;
        float t3r = a1r - a3r, t3i = a1i - a3i;
        float y0r = t0r + t2r, y0i = t0i + t2i;
        float u1r = t1r - t3i, u1i = t1i + t3r;
        float u2r = t0r - t2r, u2i = t0i - t2i;
        float u3r = t1r + t3i, u3i = t1i - t3r;
        int idx = 2 * j * m;
        float w1c = twc[idx], w1s = -tws[idx];
        float w2c = w1c*w1c - w1s*w1s, w2s = 2.f*w1c*w1s;
        float w3c = w2c*w1c - w2s*w1s, w3s = w2c*w1s + w2s*w1c;
        int o = 4 * m * j + k;
        dr[SP(o)]       = y0r;                  di[SP(o)]       = y0i;
        dr[SP(o+m)]     = u1r*w1c - u1i*w1s;    di[SP(o+m)]     = u1r*w1s + u1i*w1c;
        dr[SP(o+2*m)]   = u2r*w2c - u2i*w2s;    di[SP(o+2*m)]   = u2r*w2s + u2i*w2c;
        dr[SP(o+3*m)]   = u3r*w3c - u3i*w3s;    di[SP(o+3*m)]   = u3r*w3s + u3i*w3c;
        GBAR(bid);
    }

    // Stage 3 (twiddle-free).
    {
        float a0r = Ar_[SP(t)],       a0i = Ai_[SP(t)];
        float a1r = Ar_[SP(t + 64)],  a1i = Ai_[SP(t + 64)];
        float a2r = Ar_[SP(t + 128)], a2i = Ai_[SP(t + 128)];
        float a3r = Ar_[SP(t + 192)], a3i = Ai_[SP(t + 192)];
        float t0r = a0r + a2r, t0i = a0i + a2i;
        float t1r = a0r - a2r, t1i = a0i - a2i;
        float t2r = a1r + a3r, t2i = a1i + a3i;
        float t3r = a1r - a3r, t3i = a1i - a3i;
        v[0] = make_float2(t0r + t2r, t0i + t2i);
        v[1] = make_float2(t1r - t3i, t1i + t3r);
        v[2] = make_float2(t0r - t2r, t0i - t2i);
        v[3] = make_float2(t1r + t3i, t1i - t3r);
    }
}

// ---------------------------------------------------------------------------
// Kernel 3: single-launch irfft + overlap-add, pure writes.
// CTA b owns output segments [7b, 7b+7); it irffts the 8 contributing frames
// 7b-1 .. 7b+6 (2 rounds x 4 parallel 64-thread groups), combines
// x_{j-1}[256:] + x_j[:256] in shared, and writes each 256-sample segment
// exactly once (no RMW, no atomics, no zero pass).
// ---------------------------------------------------------------------------
__global__ void __launch_bounds__(256) inv_kernel(float* __restrict__ out) {
    __shared__ float Ar[4][264], Ai[4][264], Br[4][264], Bi[4][264];
    __shared__ float twc[257], tws[257];
    __shared__ float blockbuf[4][516];   // 512 + pad
    int t = threadIdx.x & 63, g = threadIdx.x >> 6;
    int bid = g + 1;
    int tt = threadIdx.x;
    int s0 = blockIdx.x * SEGS;          // first owned segment

    { int k = tt;
      twc[k] = g_twc[k]; tws[k] = g_tws[k];
      if (k == 0) { twc[256] = g_twc[256]; tws[256] = g_tws[256]; } }
    __syncthreads();

    float carry = 0.f;
#pragma unroll 1
    for (int r = 0; r < 2; ++r) {
        int f = s0 - 1 + 4 * r + g;      // frame this group irffts
        if (f >= 0 && f < N_ITER) {
            float2 v[4];
            irfft512(g_zr + (size_t)f * NB, g_zi + (size_t)f * NB,
                     Ar[g], Ai[g], Br[g], Bi[g], twc, tws, t, bid, v);
#pragma unroll
            for (int h = 0; h < 4; ++h) {
                int n = t + 64 * h;
                blockbuf[g][2 * n]     = v[h].x;
                blockbuf[g][2 * n + 1] = v[h].y;
            }
        } else if (f < 0) {              // frame -1 doesn't exist: zeros
            for (int n = t; n < 512; n += 64) blockbuf[g][n] = 0.f;
        }
        __syncthreads();

        if (r == 0) {
            // blocks 0..3 = frames s0-1..s0+2 -> segments s0..s0+2
#pragma unroll
            for (int q = 0; q < 3; ++q) {
                int j = s0 + q;
                if (j < N_ITER)
                    out[(size_t)j * 256 + tt] =
                        blockbuf[q][256 + tt] + blockbuf[q + 1][tt];
            }
            carry = blockbuf[3][256 + tt];   // x_{s0+2}[256:]
        } else {
            // blocks 0..3 = frames s0+3..s0+6 -> segments s0+3..s0+6
            if (s0 + 3 < N_ITER)
                out[(size_t)(s0 + 3) * 256 + tt] = carry + blockbuf[0][tt];
#pragma unroll
            for (int q = 0; q < 3; ++q) {
                int j = s0 + 4 + q;
                if (j < N_ITER)
                    out[(size_t)j * 256 + tt] =
                        blockbuf[q][256 + tt] + blockbuf[q + 1][tt];
            }
        }
        __syncthreads();   // blockbuf consumed before round 2 overwrites
    }
}

// ---------------------------------------------------------------------------
extern "C" void kernel_launch(void* const* d_in, const int* in_sizes, int n_in,
                              void* d_out, int out_size) {
    const float* noise = nullptr;
    const float* env = nullptr;
    const float* tfr = nullptr;
    const float* tfi = nullptr;
    for (int i = 0; i < n_in; ++i) {
        if (in_sizes[i] == 16777216) noise = (const float*)d_in[i];          // [32768, 512]
        else if (in_sizes[i] == 32770) env = (const float*)d_in[i];          // [32770]
        else if (in_sizes[i] == 8421890) {                                   // [32770, 257] x2
            if (!tfr) tfr = (const float*)d_in[i];
            else      tfi = (const float*)d_in[i];
        }
    }
    float* out = (float*)d_out;

    tw_init_kernel<<<1, 288>>>();
    fwd_kernel<<<N_ITER / FPB, 256>>>(noise, env);
    recur_kernel<<<N_ITER / CHUNK, 288>>>(tfr, tfi);
    inv_kernel<<<(N_ITER + SEGS - 1) / SEGS, 256>>>(out);
}

// round 16
// speedup vs baseline: 1.5051x; 1.5051x over previous
#include <cuda_runtime.h>
#include <cuda_fp16.h>
#include <math.h>

#define N_ITER 32768
#define NB 257
#define PIANO 8388608
#define CHUNK 32
#define WARM 8
#define FPB 4   // frames per CTA (256 threads = 4 groups of 64)

// padded shared index: break 32-float bank periodicity
#define SP(i) ((i) + ((i) >> 5))

#define GBAR(id) asm volatile("bar.sync %0, 64;" :: "r"(id) : "memory")

// Frequency-domain scratch planes in packed half2 (r,i) — halves traffic.
__device__ __half2 g_eh[N_ITER * NB];
__device__ __half2 g_z[N_ITER * NB];
__device__ float g_twc[257], g_tws[257];   // e^{-i*pi*k/256}

__global__ void tw_init_kernel() {
    int k = threadIdx.x;
    if (k < 257) {
        float s, c;
        sincospif(-(float)k / 256.f, &s, &c);
        g_twc[k] = c; g_tws[k] = s;
    }
}

// ---------------------------------------------------------------------------
// Kernel 1: impulse gen + 512-pt real FFT as 256-pt complex radix-4 Stockham.
// Stage 0 fused with global load; stage 3 twiddle-free. Group-local named
// barriers decouple the 4 frames per 256-thread CTA.
// ---------------------------------------------------------------------------
__global__ void __launch_bounds__(256) fwd_kernel(const float* __restrict__ noise,
                                                  const float* __restrict__ env) {
    __shared__ float Ar[FPB][264], Ai[FPB][264], Br[FPB][264], Bi[FPB][264];
    __shared__ float twc[257], tws[257];
    int t = threadIdx.x & 63, g = threadIdx.x >> 6;
    int bid = g + 1;
    int f = blockIdx.x * FPB + g;

    { int k = threadIdx.x;
      twc[k] = g_twc[k]; tws[k] = g_tws[k];
      if (k == 0) { twc[256] = g_twc[256]; tws[256] = g_tws[256]; } }

    float e = env[f];
    float amp = e * e;
    const float2* nf2 = (const float2*)(noise + (size_t)f * 512);
    float x0r, x0i, x1r, x1i, x2r, x2i, x3r, x3i;
    { float2 v = nf2[t];       x0r = (2.f*v.x-1.f)*amp; x0i = (2.f*v.y-1.f)*amp; }
    { float2 v = nf2[t + 64];  x1r = (2.f*v.x-1.f)*amp; x1i = (2.f*v.y-1.f)*amp; }
    { float2 v = nf2[t + 128]; x2r = (2.f*v.x-1.f)*amp; x2i = (2.f*v.y-1.f)*amp; }
    { float2 v = nf2[t + 192]; x3r = (2.f*v.x-1.f)*amp; x3i = (2.f*v.y-1.f)*amp; }
    __syncthreads();   // table ready (block-wide, once)

    // Stage 0 (m=1, j=t) in registers -> A.
    {
        float t0r = x0r + x2r, t0i = x0i + x2i;
        float t1r = x0r - x2r, t1i = x0i - x2i;
        float t2r = x1r + x3r, t2i = x1i + x3i;
        float t3r = x1r - x3r, t3i = x1i - x3i;
        float y0r = t0r + t2r, y0i = t0i + t2i;
        float u1r = t1r + t3i, u1i = t1i - t3r;
        float u2r = t0r - t2r, u2i = t0i - t2i;
        float u3r = t1r - t3i, u3i = t1i + t3r;
        float w1c = twc[2 * t], w1s = tws[2 * t];
        float w2c = w1c*w1c - w1s*w1s, w2s = 2.f*w1c*w1s;
        float w3c = w2c*w1c - w2s*w1s, w3s = w2c*w1s + w2s*w1c;
        int o = 4 * t;
        Ar[g][SP(o)]   = y0r;                  Ai[g][SP(o)]   = y0i;
        Ar[g][SP(o+1)] = u1r*w1c - u1i*w1s;    Ai[g][SP(o+1)] = u1r*w1s + u1i*w1c;
        Ar[g][SP(o+2)] = u2r*w2c - u2i*w2s;    Ai[g][SP(o+2)] = u2r*w2s + u2i*w2c;
        Ar[g][SP(o+3)] = u3r*w3c - u3i*w3s;    Ai[g][SP(o+3)] = u3r*w3s + u3i*w3c;
    }
    GBAR(bid);

    // Stages 1-2 through shared (A->B->A).
#pragma unroll
    for (int r = 1; r < 3; ++r) {
        int m = 1 << (2 * r);
        int k = t & (m - 1);
        int j = t >> (2 * r);
        const float (*srcr)[264] = (r == 1) ? Ar : Br;
        const float (*srci)[264] = (r == 1) ? Ai : Bi;
        float (*dstr)[264] = (r == 1) ? Br : Ar;
        float (*dsti)[264] = (r == 1) ? Bi : Ai;
        float a0r = srcr[g][SP(t)],       a0i = srci[g][SP(t)];
        float a1r = srcr[g][SP(t + 64)],  a1i = srci[g][SP(t + 64)];
        float a2r = srcr[g][SP(t + 128)], a2i = srci[g][SP(t + 128)];
        float a3r = srcr[g][SP(t + 192)], a3i = srci[g][SP(t + 192)];
        float t0r = a0r + a2r, t0i = a0i + a2i;
        float t1r = a0r - a2r, t1i = a0i - a2i;
        float t2r = a1r + a3r, t2i = a1i + a3i;
        float t3r = a1r - a3r, t3i = a1i - a3i;
        float y0r = t0r + t2r, y0i = t0i + t2i;
        float u1r = t1r + t3i, u1i = t1i - t3r;
        float u2r = t0r - t2r, u2i = t0i - t2i;
        float u3r = t1r - t3i, u3i = t1i + t3r;
        int idx = 2 * j * m;
        float w1c = twc[idx], w1s = tws[idx];
        float w2c = w1c*w1c - w1s*w1s, w2s = 2.f*w1c*w1s;
        float w3c = w2c*w1c - w2s*w1s, w3s = w2c*w1s + w2s*w1c;
        int o = 4 * m * j + k;
        dstr[g][SP(o)]       = y0r;                  dsti[g][SP(o)]       = y0i;
        dstr[g][SP(o+m)]     = u1r*w1c - u1i*w1s;    dsti[g][SP(o+m)]     = u1r*w1s + u1i*w1c;
        dstr[g][SP(o+2*m)]   = u2r*w2c - u2i*w2s;    dsti[g][SP(o+2*m)]   = u2r*w2s + u2i*w2c;
        dstr[g][SP(o+3*m)]   = u3r*w3c - u3i*w3s;    dsti[g][SP(o+3*m)]   = u3r*w3s + u3i*w3c;
        GBAR(bid);
    }

    // Stage 3 (m=64, j=0: twiddles = 1) -> Z[t+64h] unpadded in B.
    {
        float a0r = Ar[g][SP(t)],       a0i = Ai[g][SP(t)];
        float a1r = Ar[g][SP(t + 64)],  a1i = Ai[g][SP(t + 64)];
        float a2r = Ar[g][SP(t + 128)], a2i = Ai[g][SP(t + 128)];
        float a3r = Ar[g][SP(t + 192)], a3i = Ai[g][SP(t + 192)];
        float t0r = a0r + a2r, t0i = a0i + a2i;
        float t1r = a0r - a2r, t1i = a0i - a2i;
        float t2r = a1r + a3r, t2i = a1i + a3i;
        float t3r = a1r - a3r, t3i = a1i - a3i;
        Br[g][t]       = t0r + t2r;  Bi[g][t]       = t0i + t2i;
        Br[g][t + 64]  = t1r + t3i;  Bi[g][t + 64]  = t1i - t3r;
        Br[g][t + 128] = t0r - t2r;  Bi[g][t + 128] = t0i - t2i;
        Br[g][t + 192] = t1r - t3i;  Bi[g][t + 192] = t1i + t3r;
    }
    GBAR(bid);

    // Untangle 256-pt complex FFT Z into 257-bin rfft -> half2 plane.
    __half2* ehp = g_eh + (size_t)f * NB;
#pragma unroll
    for (int h = 0; h < 4; ++h) {
        int k = t + 64 * h;
        int k2 = (256 - k) & 255;
        float Arv = Br[g][k],  Aiv = Bi[g][k];
        float Crv = Br[g][k2], Civ = Bi[g][k2];
        float Xer = 0.5f * (Arv + Crv), Xei = 0.5f * (Aiv - Civ);
        float Dr  = 0.5f * (Arv - Crv), Di  = 0.5f * (Aiv + Civ);
        float Xor = Di, Xoi = -Dr;                 // -i*D
        float c = twc[k], s = tws[k];
        ehp[k] = __floats2half2_rn(Xer + Xor * c - Xoi * s,
                                   Xei + Xor * s + Xoi * c);
    }
    if (t == 0) {
        ehp[256] = __floats2half2_rn(Br[g][0] - Bi[g][0], 0.f);
    }
}

// ---------------------------------------------------------------------------
// Kernel 2: chunk-parallel frequency-domain recurrence.
//   y_i = T * P(tf_i .* (y_{i-1} + ehat_i)),  z_i = y_{i-1} + ehat_i stored.
// T tridiagonal circulant (0.54, -0.23, -0.23); contraction |tf|<=0.283 lets
// each chunk warm up from zero in WARM steps (0.283^8 ~ 4e-5).
// ---------------------------------------------------------------------------
__global__ void __launch_bounds__(288) recur_kernel(const float* __restrict__ tfr_g,
                                                    const float* __restrict__ tfi_g) {
    __shared__ float2 gbuf[2][260];
    int c = blockIdx.x, t = threadIdx.x;
    int start = c * CHUNK;
    int i0 = start - WARM;
    if (i0 < 0) i0 = 0;
    int end = start + CHUNK;
    bool act = (t < NB);
    int k = act ? t : 0;

    float yr = 0.f, yi = 0.f;
    float er = 0.f, ei = 0.f, tr = 0.f, ti = 0.f;
    if (act) {
        size_t b = (size_t)i0 * NB + k;
        float2 ef = __half22float2(g_eh[b]);
        er = ef.x; ei = ef.y;
        tr = tfr_g[b]; ti = tfi_g[b];
    }
    int p = 0;
    for (int i = i0; i < end; ++i) {
        float cer = er, cei = ei, ctr = tr, cti = ti;
        if (act && (i + 1 < end)) {  // prefetch next frame (independent of y)
            size_t b2 = (size_t)(i + 1) * NB + k;
            float2 ef = __half22float2(g_eh[b2]);
            er = ef.x; ei = ef.y;
            tr = tfr_g[b2]; ti = tfi_g[b2];
        }
        float zr = yr + cer, zi = yi + cei;
        if (act && i >= start) {
            g_z[(size_t)i * NB + k] = __floats2half2_rn(zr, zi);
        }
        float gr = ctr * zr - cti * zi;
        float gi = ctr * zi + cti * zr;
        if (k == 0 || k == 256) gi = 0.f;  // P: irfft drops imag at DC/Nyquist
        if (act) {
            gbuf[p][k + 1] = make_float2(gr, gi);
            if (k == 1)   gbuf[p][0]   = make_float2(gr, -gi);
            if (k == 255) gbuf[p][258] = make_float2(gr, -gi);
        }
        __syncthreads();
        if (act) {
            float2 L = gbuf[p][k];
            float2 R = gbuf[p][k + 2];
            yr = 0.54f * gr - 0.23f * (L.x + R.x);
            yi = 0.54f * gi - 0.23f * (L.y + R.y);
        }
        p ^= 1;
    }
}

// ---------------------------------------------------------------------------
// Kernels 3/4: batched 512-pt irfft + overlap-add. Untangle+stage0 fused in
// registers; stage 3 twiddle-free, writes straight to global (coalesced).
// 4 frames per 256-thread CTA; group-local named barriers.
// ---------------------------------------------------------------------------
__global__ void __launch_bounds__(256) inv_kernel(float* __restrict__ out, int parity) {
    __shared__ float Ar[FPB][264], Ai[FPB][264], Br[FPB][264], Bi[FPB][264];
    __shared__ float twc[257], tws[257];
    int t = threadIdx.x & 63, g = threadIdx.x >> 6;
    int bid = g + 1;
    int f = (blockIdx.x * FPB + g) * 2 + parity;

    { int k = threadIdx.x;
      twc[k] = g_twc[k]; tws[k] = g_tws[k];
      if (k == 0) { twc[256] = g_twc[256]; tws[256] = g_tws[256]; } }

    // Stage z spectrum (257 half2 entries) into B (unpadded).
    const __half2* zp = g_z + (size_t)f * NB;
    __syncthreads();   // table ready
    for (int k = t; k < 257; k += 64) {
        float2 zv = __half22float2(zp[k]);
        Br[g][k] = zv.x; Bi[g][k] = zv.y;
    }
    GBAR(bid);

    // Untangle -> Z[k] for k = t+64h (registers), then stage 0 -> A.
    float zkr[4], zki[4];
#pragma unroll
    for (int h = 0; h < 4; ++h) {
        int k = t + 64 * h;
        float Arv = Br[g][k],       Aiv = Bi[g][k];
        float Crv = Br[g][256 - k], Civ = Bi[g][256 - k];
        float Xer = 0.5f * (Arv + Crv), Xei = 0.5f * (Aiv - Civ);
        float Dr  = 0.5f * (Arv - Crv), Di  = 0.5f * (Aiv + Civ);
        float c = twc[k], s = -tws[k];            // e^{+i*pi*k/256}
        float Xor = Dr * c - Di * s;
        float Xoi = Dr * s + Di * c;
        zkr[h] = (Xer - Xoi) * (1.f / 256.f);
        zki[h] = (Xei + Xor) * (1.f / 256.f);
    }
    {
        float t0r = zkr[0] + zkr[2], t0i = zki[0] + zki[2];
        float t1r = zkr[0] - zkr[2], t1i = zki[0] - zki[2];
        float t2r = zkr[1] + zkr[3], t2i = zki[1] + zki[3];
        float t3r = zkr[1] - zkr[3], t3i = zki[1] - zki[3];
        float y0r = t0r + t2r, y0i = t0i + t2i;
        float u1r = t1r - t3i, u1i = t1i + t3r;   // inverse orientation
        float u2r = t0r - t2r, u2i = t0i - t2i;
        float u3r = t1r + t3i, u3i = t1i - t3r;
        float w1c = twc[2 * t], w1s = -tws[2 * t];
        float w2c = w1c*w1c - w1s*w1s, w2s = 2.f*w1c*w1s;
        float w3c = w2c*w1c - w2s*w1s, w3s = w2c*w1s + w2s*w1c;
        int o = 4 * t;
        Ar[g][SP(o)]   = y0r;                  Ai[g][SP(o)]   = y0i;
        Ar[g][SP(o+1)] = u1r*w1c - u1i*w1s;    Ai[g][SP(o+1)] = u1r*w1s + u1i*w1c;
        Ar[g][SP(o+2)] = u2r*w2c - u2i*w2s;    Ai[g][SP(o+2)] = u2r*w2s + u2i*w2c;
        Ar[g][SP(o+3)] = u3r*w3c - u3i*w3s;    Ai[g][SP(o+3)] = u3r*w3s + u3i*w3c;
    }
    GBAR(bid);

    // Stages 1-2 (A->B->A), inverse twiddles.
#pragma unroll
    for (int r = 1; r < 3; ++r) {
        int m = 1 << (2 * r);
        int k = t & (m - 1);
        int j = t >> (2 * r);
        const float (*srcr)[264] = (r == 1) ? Ar : Br;
        const float (*srci)[264] = (r == 1) ? Ai : Bi;
        float (*dstr)[264] = (r == 1) ? Br : Ar;
        float (*dsti)[264] = (r == 1) ? Bi : Ai;
        float a0r = srcr[g][SP(t)],       a0i = srci[g][SP(t)];
        float a1r = srcr[g][SP(t + 64)],  a1i = srci[g][SP(t + 64)];
        float a2r = srcr[g][SP(t + 128)], a2i = srci[g][SP(t + 128)];
        float a3r = srcr[g][SP(t + 192)], a3i = srci[g][SP(t + 192)];
        float t0r = a0r + a2r, t0i = a0i + a2i;
        float t1r = a0r - a2r, t1i = a0i - a2i;
        float t2r = a1r + a3r, t2i = a1i + a3i;
        float t3r = a1r - a3r, t3i = a1i - a3i;
        float y0r = t0r + t2r, y0i = t0i + t2i;
        float u1r = t1r - t3i, u1i = t1i + t3r;
        float u2r = t0r - t2r, u2i = t0i - t2i;
        float u3r = t1r + t3i, u3i = t1i - t3r;
        int idx = 2 * j * m;
        float w1c = twc[idx], w1s = -tws[idx];
        float w2c = w1c*w1c - w1s*w1s, w2s = 2.f*w1c*w1s;
        float w3c = w2c*w1c - w2s*w1s, w3s = w2c*w1s + w2s*w1c;
        int o = 4 * m * j + k;
        dstr[g][SP(o)]       = y0r;                  dsti[g][SP(o)]       = y0i;
        dstr[g][SP(o+m)]     = u1r*w1c - u1i*w1s;    dsti[g][SP(o+m)]     = u1r*w1s + u1i*w1c;
        dstr[g][SP(o+2*m)]   = u2r*w2c - u2i*w2s;    dsti[g][SP(o+2*m)]   = u2r*w2s + u2i*w2c;
        dstr[g][SP(o+3*m)]   = u3r*w3c - u3i*w3s;    dsti[g][SP(o+3*m)]   = u3r*w3s + u3i*w3c;
        GBAR(bid);
    }

    // Stage 3 (twiddle-free) -> x[2n]+i*x[2n+1] at n = t+64h -> global.
    {
        float a0r = Ar[g][SP(t)],       a0i = Ai[g][SP(t)];
        float a1r = Ar[g][SP(t + 64)],  a1i = Ai[g][SP(t + 64)];
        float a2r = Ar[g][SP(t + 128)], a2i = Ai[g][SP(t + 128)];
        float a3r = Ar[g][SP(t + 192)], a3i = Ai[g][SP(t + 192)];
        float t0r = a0r + a2r, t0i = a0i + a2i;
        float t1r = a0r - a2r, t1i = a0i - a2i;
        float t2r = a1r + a3r, t2i = a1i + a3i;
        float t3r = a1r - a3r, t3i = a1i - a3i;
        float2 v[4];
        v[0] = make_float2(t0r + t2r, t0i + t2i);
        v[1] = make_float2(t1r - t3i, t1i + t3r);
        v[2] = make_float2(t0r - t2r, t0i - t2i);
        v[3] = make_float2(t1r + t3i, t1i - t3r);
        size_t base = (size_t)f * 256;
        float2* o2 = (float2*)(out + base);
#pragma unroll
        for (int h = 0; h < 4; ++h) {
            int n = t + 64 * h;
            if (parity == 0) {
                o2[n] = v[h];
            } else if (base + 2 * (size_t)n + 1 < (size_t)PIANO) {
                float2 cur = o2[n];
                o2[n] = make_float2(cur.x + v[h].x, cur.y + v[h].y);
            }
        }
    }
}

// ---------------------------------------------------------------------------
extern "C" void kernel_launch(void* const* d_in, const int* in_sizes, int n_in,
                              void* d_out, int out_size) {
    const float* noise = nullptr;
    const float* env = nullptr;
    const float* tfr = nullptr;
    const float* tfi = nullptr;
    for (int i = 0; i < n_in; ++i) {
        if (in_sizes[i] == 16777216) noise = (const float*)d_in[i];          // [32768, 512]
        else if (in_sizes[i] == 32770) env = (const float*)d_in[i];          // [32770]
        else if (in_sizes[i] == 8421890) {                                   // [32770, 257] x2
            if (!tfr) tfr = (const float*)d_in[i];
            else      tfi = (const float*)d_in[i];
        }
    }
    float* out = (float*)d_out;

    tw_init_kernel<<<1, 288>>>();
    fwd_kernel<<<N_ITER / FPB, 256>>>(noise, env);
    recur_kernel<<<N_ITER / CHUNK, 288>>>(tfr, tfi);
    inv_kernel<<<N_ITER / (2 * FPB), 256>>>(out, 0);
    inv_kernel<<<N_ITER / (2 * FPB), 256>>>(out, 1);
}

// round 17
// speedup vs baseline: 1.6012x; 1.0638x over previous
#include <cuda_runtime.h>
#include <cuda_fp16.h>
#include <math.h>

#define N_ITER 32768
#define NB 257
#define PIANO 8388608
#define CHUNK 32
#define WARM 8

// padded shared index: conflict-free for both k2+8q scatter and k gather
#define SP(i) ((i) + ((i) >> 5))

// Frequency-domain scratch planes in packed half2 (r,i).
__device__ __half2 g_eh[N_ITER * NB];
__device__ __half2 g_z[N_ITER * NB];
__device__ float g_c512[512], g_s512[512];   // cos/sin(pi*m/256) = 2pi*m/512

__global__ void tw_init_kernel() {
    int m = threadIdx.x;
    float s, c;
    sincospif((float)m / 256.f, &s, &c);
    g_c512[m] = c; g_s512[m] = s;
}

__device__ __forceinline__ void cmul(float& ar, float& ai, float c, float s) {
    float r = ar * c - ai * s;
    ai = ar * s + ai * c;
    ar = r;
}

// 8-point DFT in registers, natural order in/out. SGN=-1 fwd, +1 inv.
template<int SGN>
__device__ __forceinline__ void fft8(float xr[8], float xi[8]) {
    const float S = 0.70710678118654752f;
    float t0r = xr[0] + xr[4], t0i = xi[0] + xi[4];
    float t1r = xr[0] - xr[4], t1i = xi[0] - xi[4];
    float t2r = xr[2] + xr[6], t2i = xi[2] + xi[6];
    float t3r = xr[2] - xr[6], t3i = xi[2] - xi[6];
    float E0r = t0r + t2r, E0i = t0i + t2i;
    float E2r = t0r - t2r, E2i = t0i - t2i;
    float E1r = t1r - SGN * t3i, E1i = t1i + SGN * t3r;
    float E3r = t1r + SGN * t3i, E3i = t1i - SGN * t3r;
    float u0r = xr[1] + xr[5], u0i = xi[1] + xi[5];
    float u1r = xr[1] - xr[5], u1i = xi[1] - xi[5];
    float u2r = xr[3] + xr[7], u2i = xi[3] + xi[7];
    float u3r = xr[3] - xr[7], u3i = xi[3] - xi[7];
    float O0r = u0r + u2r, O0i = u0i + u2i;
    float O2r = u0r - u2r, O2i = u0i - u2i;
    float O1r = u1r - SGN * u3i, O1i = u1i + SGN * u3r;
    float O3r = u1r + SGN * u3i, O3i = u1i - SGN * u3r;
    cmul(O1r, O1i, S, SGN * S);              // W8^1 (conj for inv)
    cmul(O2r, O2i, 0.f, (float)SGN);         // W8^2 = -+i
    cmul(O3r, O3i, -S, SGN * S);             // W8^3
    xr[0] = E0r + O0r; xi[0] = E0i + O0i;
    xr[4] = E0r - O0r; xi[4] = E0i - O0i;
    xr[1] = E1r + O1r; xi[1] = E1i + O1i;
    xr[5] = E1r - O1r; xi[5] = E1i - O1i;
    xr[2] = E2r + O2r; xi[2] = E2i + O2i;
    xr[6] = E2r - O2r; xi[6] = E2i - O2i;
    xr[3] = E3r + O3r; xi[3] = E3i + O3i;
    xr[7] = E3r - O3r; xi[7] = E3i - O3i;
}

// 32-point DFT across lanes (radix-2 DIF via shfl_xor). Natural input on
// lane n1; output for k1=bitrev5(lane) on each lane. 8 independent columns.
template<int SGN>
__device__ __forceinline__ void lane_fft(float vr[8], float vi[8],
                                         const float* __restrict__ c512,
                                         const float* __restrict__ s512,
                                         int lane) {
#pragma unroll
    for (int s = 0; s < 5; ++s) {
        int H = 16 >> s;
        int bot = lane & H;
        int m = lane & (H - 1);
        int idx = m << (4 + s);              // W_{2H}^m -> tw512[m*256/H]
        float c = c512[idx];
        float sn = SGN * s512[idx];
#pragma unroll
        for (int q = 0; q < 8; ++q) {
            float pr = __shfl_xor_sync(0xffffffffu, vr[q], H);
            float pi = __shfl_xor_sync(0xffffffffu, vi[q], H);
            float nr, ni;
            if (!bot) { nr = vr[q] + pr; ni = vi[q] + pi; }
            else {
                float dr = pr - vr[q], di = pi - vi[q];
                nr = dr * c - di * sn;
                ni = dr * sn + di * c;
            }
            vr[q] = nr; vi[q] = ni;
        }
    }
}

// ---------------------------------------------------------------------------
// Kernel 1: impulse gen + 512-pt real FFT. One frame per WARP (8/CTA).
// Four-step shuffle FFT; one syncwarp-staged shared round for the untangle.
// ---------------------------------------------------------------------------
__global__ void __launch_bounds__(256) fwd_kernel(const float* __restrict__ noise,
                                                  const float* __restrict__ env) {
    __shared__ float c512[512], s512[512];
    __shared__ float Zr[8][268], Zi[8][268];
    int l = threadIdx.x & 31, w = threadIdx.x >> 5;
    int f = blockIdx.x * 8 + w;
    { int k = threadIdx.x;
      c512[k] = g_c512[k];         s512[k] = g_s512[k];
      c512[k + 256] = g_c512[k + 256]; s512[k + 256] = g_s512[k + 256]; }

    float e = env[f];
    float amp = e * e;
    const float2* nf2 = (const float2*)(noise + (size_t)f * 512);
    float xr[8], xi[8];
#pragma unroll
    for (int j = 0; j < 8; ++j) {            // x_c[l+32j] = imp[2n]+i*imp[2n+1]
        float2 v = nf2[l + 32 * j];
        xr[j] = (2.f * v.x - 1.f) * amp;
        xi[j] = (2.f * v.y - 1.f) * amp;
    }
    __syncthreads();                          // tables ready

    fft8<-1>(xr, xi);                         // DFT over reg index n2
#pragma unroll
    for (int k2 = 1; k2 < 8; ++k2)            // W_256^{l*k2}
        cmul(xr[k2], xi[k2], c512[2 * l * k2], -s512[2 * l * k2]);
    lane_fft<-1>(xr, xi, c512, s512, l);      // DFT across lanes

    int qrev = __brev(l) >> 27;               // lane holds X[k2 + 8*qrev]
#pragma unroll
    for (int k2 = 0; k2 < 8; ++k2) {
        Zr[w][SP(k2 + 8 * qrev)] = xr[k2];
        Zi[w][SP(k2 + 8 * qrev)] = xi[k2];
    }
    __syncwarp();

    // Hermitian untangle -> 257-bin rfft -> half2 plane.
    __half2* ehp = g_eh + (size_t)f * NB;
#pragma unroll
    for (int j = 0; j < 8; ++j) {
        int k = l + 32 * j;
        int k2 = (256 - k) & 255;
        float Arv = Zr[w][SP(k)],  Aiv = Zi[w][SP(k)];
        float Crv = Zr[w][SP(k2)], Civ = Zi[w][SP(k2)];
        float Xer = 0.5f * (Arv + Crv), Xei = 0.5f * (Aiv - Civ);
        float Dr  = 0.5f * (Arv - Crv), Di  = 0.5f * (Aiv + Civ);
        float Xor = Di, Xoi = -Dr;            // -i*D
        float c = c512[k], s = -s512[k];      // e^{-i*pi*k/256}
        ehp[k] = __floats2half2_rn(Xer + Xor * c - Xoi * s,
                                   Xei + Xor * s + Xoi * c);
    }
    if (l == 0)
        ehp[256] = __floats2half2_rn(Zr[w][SP(0)] - Zi[w][SP(0)], 0.f);
}

// ---------------------------------------------------------------------------
// Kernel 2: chunk-parallel frequency-domain recurrence (unchanged, passing).
// ---------------------------------------------------------------------------
__global__ void __launch_bounds__(288) recur_kernel(const float* __restrict__ tfr_g,
                                                    const float* __restrict__ tfi_g) {
    __shared__ float2 gbuf[2][260];
    int c = blockIdx.x, t = threadIdx.x;
    int start = c * CHUNK;
    int i0 = start - WARM;
    if (i0 < 0) i0 = 0;
    int end = start + CHUNK;
    bool act = (t < NB);
    int k = act ? t : 0;

    float yr = 0.f, yi = 0.f;
    float er = 0.f, ei = 0.f, tr = 0.f, ti = 0.f;
    if (act) {
        size_t b = (size_t)i0 * NB + k;
        float2 ef = __half22float2(g_eh[b]);
        er = ef.x; ei = ef.y;
        tr = tfr_g[b]; ti = tfi_g[b];
    }
    int p = 0;
    for (int i = i0; i < end; ++i) {
        float cer = er, cei = ei, ctr = tr, cti = ti;
        if (act && (i + 1 < end)) {
            size_t b2 = (size_t)(i + 1) * NB + k;
            float2 ef = __half22float2(g_eh[b2]);
            er = ef.x; ei = ef.y;
            tr = tfr_g[b2]; ti = tfi_g[b2];
        }
        float zr = yr + cer, zi = yi + cei;
        if (act && i >= start) {
            g_z[(size_t)i * NB + k] = __floats2half2_rn(zr, zi);
        }
        float gr = ctr * zr - cti * zi;
        float gi = ctr * zi + cti * zr;
        if (k == 0 || k == 256) gi = 0.f;
        if (act) {
            gbuf[p][k + 1] = make_float2(gr, gi);
            if (k == 1)   gbuf[p][0]   = make_float2(gr, -gi);
            if (k == 255) gbuf[p][258] = make_float2(gr, -gi);
        }
        __syncthreads();
        if (act) {
            float2 L = gbuf[p][k];
            float2 R = gbuf[p][k + 2];
            yr = 0.54f * gr - 0.23f * (L.x + R.x);
            yi = 0.54f * gi - 0.23f * (L.y + R.y);
        }
        p ^= 1;
    }
}

// ---------------------------------------------------------------------------
// Kernels 3/4: 512-pt irfft + overlap-add. One frame per WARP; untangle reads
// straight from global (both access streams coalesced), zero shared/barriers
// in the FFT path; output as 4 aligned float4 per lane.
// ---------------------------------------------------------------------------
__global__ void __launch_bounds__(256) inv_kernel(float* __restrict__ out, int parity) {
    __shared__ float c512[512], s512[512];
    int l = threadIdx.x & 31, w = threadIdx.x >> 5;
    int f = (blockIdx.x * 8 + w) * 2 + parity;
    { int k = threadIdx.x;
      c512[k] = g_c512[k];         s512[k] = g_s512[k];
      c512[k + 256] = g_c512[k + 256]; s512[k + 256] = g_s512[k + 256]; }
    __syncthreads();

    const __half2* zp = g_z + (size_t)f * NB;
    float xr[8], xi[8];
#pragma unroll
    for (int j = 0; j < 8; ++j) {             // untangle -> Z[l+32j] in regs
        int k = l + 32 * j;
        float2 A = __half22float2(zp[k]);
        float2 C = __half22float2(zp[256 - k]);
        float Xer = 0.5f * (A.x + C.x), Xei = 0.5f * (A.y - C.y);
        float Dr  = 0.5f * (A.x - C.x), Di  = 0.5f * (A.y + C.y);
        float c = c512[k], s = s512[k];       // e^{+i*pi*k/256}
        float Xor = Dr * c - Di * s;
        float Xoi = Dr * s + Di * c;
        xr[j] = (Xer - Xoi) * (1.f / 256.f);
        xi[j] = (Xei + Xor) * (1.f / 256.f);
    }

    fft8<1>(xr, xi);                          // inverse: conjugated twiddles
#pragma unroll
    for (int k2 = 1; k2 < 8; ++k2)
        cmul(xr[k2], xi[k2], c512[2 * l * k2], s512[2 * l * k2]);
    lane_fft<1>(xr, xi, c512, s512, l);

    int qrev = __brev(l) >> 27;               // lane holds x_c[k2 + 8*qrev]
    // x_c[m] = x[2m] + i*x[2m+1]: lane covers 16 consecutive floats at 16*qrev.
    float4* o4 = (float4*)out + (size_t)f * 64 + 4 * qrev;
#pragma unroll
    for (int i = 0; i < 4; ++i) {
        float4 v = make_float4(xr[2 * i], xi[2 * i], xr[2 * i + 1], xi[2 * i + 1]);
        if (parity == 0) {
            o4[i] = v;                        // even frames tile exactly
        } else {
            size_t gidx = (size_t)f * 64 + 4 * qrev + i;
            if (gidx < (size_t)PIANO / 4) {   // clip tail of frame 32767
                float4 cur = o4[i];
                o4[i] = make_float4(cur.x + v.x, cur.y + v.y,
                                    cur.z + v.z, cur.w + v.w);
            }
        }
    }
}

// ---------------------------------------------------------------------------
extern "C" void kernel_launch(void* const* d_in, const int* in_sizes, int n_in,
                              void* d_out, int out_size) {
    const float* noise = nullptr;
    const float* env = nullptr;
    const float* tfr = nullptr;
    const float* tfi = nullptr;
    for (int i = 0; i < n_in; ++i) {
        if (in_sizes[i] == 16777216) noise = (const float*)d_in[i];          // [32768, 512]
        else if (in_sizes[i] == 32770) env = (const float*)d_in[i];          // [32770]
        else if (in_sizes[i] == 8421890) {                                   // [32770, 257] x2
            if (!tfr) tfr = (const float*)d_in[i];
            else      tfi = (const float*)d_in[i];
        }
    }
    float* out = (float*)d_out;

    tw_init_kernel<<<1, 512>>>();
    fwd_kernel<<<N_ITER / 8, 256>>>(noise, env);
    recur_kernel<<<N_ITER / CHUNK, 288>>>(tfr, tfi);
    inv_kernel<<<N_ITER / 16, 256>>>(out, 0);
    inv_kernel<<<N_ITER / 16, 256>>>(out, 1);
}